// round 8
// baseline (speedup 1.0000x reference)
#include <cuda_runtime.h>
#include <cuda_fp16.h>
#include <cstdint>
#include <math.h>

#define TT 8192
#define NE 8
#define HD 2048
#define ID 5632
#define NROW (TT*2)

// ---------------- scratch (static device globals) ----------------
__device__ int    g_count[NE];
__device__ int    g_base[NE];
__device__ int    g_ctr[NE];
__device__ int    g_tok_e[TT*2];
__device__ float  g_tok_w[TT*2];
__device__ int    g_row_of[TT*2];
__device__ int    g_tok_of_row[NROW];
__device__ float  g_w_of_row[NROW];
__device__ __half g_xh [(size_t)TT*HD];
__device__ __half g_w1h[(size_t)NE*ID*HD];
__device__ __half g_w3h[(size_t)NE*ID*HD];
__device__ __half g_w2h[(size_t)NE*HD*ID];
__device__ __half g_act[(size_t)NROW*ID];

// ---------------- helpers ----------------
__device__ __forceinline__ void cpa16(uint32_t dst, uint64_t gsrc) {
    asm volatile("cp.async.cg.shared.global [%0], [%1], 16;" :: "r"(dst), "l"(gsrc));
}
#define CPA_COMMIT() asm volatile("cp.async.commit_group;" ::: "memory")
#define CPA_WAIT(n)  asm volatile("cp.async.wait_group %0;" :: "n"(n) : "memory")

__device__ __forceinline__ uint32_t smem_u32(const void* p) {
    uint32_t a;
    asm("{ .reg .u64 t; cvta.to.shared.u64 t, %1; cvt.u32.u64 %0, t; }" : "=r"(a) : "l"(p));
    return a;
}

__device__ __forceinline__ void mma_f16(float* c, const uint32_t* a, const uint32_t* b) {
    asm volatile(
        "mma.sync.aligned.m16n8k16.row.col.f32.f16.f16.f32 "
        "{%0,%1,%2,%3},{%4,%5,%6,%7},{%8,%9},{%0,%1,%2,%3};"
        : "+f"(c[0]), "+f"(c[1]), "+f"(c[2]), "+f"(c[3])
        : "r"(a[0]), "r"(a[1]), "r"(a[2]), "r"(a[3]), "r"(b[0]), "r"(b[1]));
}

// ---------------- routing ----------------
__global__ void zero_meta_kernel() { if (threadIdx.x < NE) g_count[threadIdx.x] = 0; }

__global__ void route_count_kernel(const float* __restrict__ logits) {
    int t = blockIdx.x * blockDim.x + threadIdx.x;
    if (t >= TT) return;
    float v[NE];
#pragma unroll
    for (int e = 0; e < NE; e++) v[e] = logits[t * NE + e];
    int i0 = 0; float m0 = v[0];
#pragma unroll
    for (int e = 1; e < NE; e++) if (v[e] > m0) { m0 = v[e]; i0 = e; }
    int i1 = -1; float m1 = -INFINITY;
#pragma unroll
    for (int e = 0; e < NE; e++) if (e != i0 && v[e] > m1) { m1 = v[e]; i1 = e; }
    float z = expf(m1 - m0);
    float w0 = 1.0f / (1.0f + z);
    g_tok_e[t*2+0] = i0; g_tok_e[t*2+1] = i1;
    g_tok_w[t*2+0] = w0; g_tok_w[t*2+1] = z * w0;
    atomicAdd(&g_count[i0], 1);
    atomicAdd(&g_count[i1], 1);
}

__global__ void scan_kernel() {
    int acc = 0;
    for (int e = 0; e < NE; e++) { g_base[e] = acc; acc += g_count[e]; g_ctr[e] = 0; }
}

__global__ void route_scatter_kernel() {
    int t = blockIdx.x * blockDim.x + threadIdx.x;
    if (t >= TT) return;
#pragma unroll
    for (int k = 0; k < 2; k++) {
        int e = g_tok_e[t*2+k];
        int slot = atomicAdd(&g_ctr[e], 1);
        int row = g_base[e] + slot;
        g_row_of[t*2+k] = row;
        g_tok_of_row[row] = t;
        g_w_of_row[row] = g_tok_w[t*2+k];
    }
}

// ---------------- fp32 -> fp16 convert (2 float4 per thread) ----------------
__global__ void to_half_kernel(const float4* __restrict__ in, uint2* __restrict__ out, int n4) {
    int i = (blockIdx.x * blockDim.x + threadIdx.x) * 2;
#pragma unroll
    for (int q = 0; q < 2; q++) {
        int j = i + q;
        if (j >= n4) return;
        float4 v = in[j];
        __half2 h0 = __floats2half2_rn(v.x, v.y);
        __half2 h1 = __floats2half2_rn(v.z, v.w);
        uint2 o;
        o.x = *reinterpret_cast<uint32_t*>(&h0);
        o.y = *reinterpret_cast<uint32_t*>(&h1);
        out[j] = o;
    }
}

// ---------------- GEMM kernels (fp16 m16n8k16, persistent CTAs) ----------------
// Block 128(M) x 128(Bcols), BK=32 halves (64B/row), 8 warps (2x4), warp tile 64x32.
// 4-stage cp.async ring; rows padded to 40 halves (word stride 20 -> conflict-free).
// Persistent grid: each CTA loops over virtual tiles (row block fastest for L2 B-share).
#define BKH  32
#define PFH  40
#define TILE_H (128*PFH)                  // halves per tile per stage (5120)
#define STG_B  (TILE_H*2)                 // 10240 bytes
#define NSTG 4
#define GEMM_SMEM (2*NSTG*STG_B)          // 81920 bytes
#define PGRID 304                          // 2 CTAs/SM x 152 SMs

// GEMM1: B rows 0..63 = w1 rows (gate), 64..127 = w3 rows (up), same 64 I-cols.
__global__ void __launch_bounds__(256, 2) gemm1_mma_kernel() {
    extern __shared__ char sm[];
    char* AsB = sm;
    char* BsB = sm + NSTG * STG_B;

    const int tid  = threadIdx.x;
    const int warp = tid >> 5;
    const int lane = tid & 31;
    const int wm = warp & 1;
    const int wn = warp >> 1;
    const int g  = lane >> 2;
    const int tg = lane & 3;

    const int lrow = tid >> 1;                 // 0..127
    const int lcol = (tid & 1) * 16;           // fp16 offset (0 or 16)

    const uint32_t aS = smem_u32(AsB) + (uint32_t)(lrow * PFH + lcol) * 2;
    const uint32_t bS = smem_u32(BsB) + (uint32_t)(lrow * PFH + lcol) * 2;

    const int NT = NE * (ID / 64) * (NROW / 128);  // 90112 virtual tiles

    for (int v = blockIdx.x; v < NT; v += PGRID) {
        const int e   = v / ((ID / 64) * (NROW / 128));
        const int r   = v % ((ID / 64) * (NROW / 128));
        const int row0 = (r & 127) * 128;          // row block fastest
        const int cnt = g_count[e];
        if (row0 >= cnt) continue;
        const int base = g_base[e];
        const int nI = (r >> 7) * 64;

        __syncthreads();   // previous tile's epilogue smem fully consumed

        int gr = row0 + lrow;
        int tok = (gr < cnt) ? g_tok_of_row[base + gr] : 0;
        const uint64_t aG = (uint64_t)__cvta_generic_to_global(g_xh + (size_t)tok * HD + lcol);
        const __half* bptr = (lrow < 64)
            ? g_w1h + ((size_t)e * ID + nI + lrow) * HD + lcol
            : g_w3h + ((size_t)e * ID + nI + (lrow - 64)) * HD + lcol;
        const uint64_t bG = (uint64_t)__cvta_generic_to_global(bptr);

        float acc[4][4][4];
#pragma unroll
        for (int i = 0; i < 4; i++)
#pragma unroll
            for (int j = 0; j < 4; j++)
#pragma unroll
                for (int q = 0; q < 4; q++) acc[i][j][q] = 0.f;

        const int NS = HD / BKH;  // 64
#pragma unroll
        for (int p = 0; p < NSTG - 1; p++) {
            uint32_t so = p * STG_B;
            uint64_t ko = (uint64_t)p * BKH * 2;
            cpa16(aS + so, aG + ko); cpa16(aS + so + 16, aG + ko + 16);
            cpa16(bS + so, bG + ko); cpa16(bS + so + 16, bG + ko + 16);
            CPA_COMMIT();
        }

        for (int s = 0; s < NS; s++) {
            CPA_WAIT(NSTG - 2);
            __syncthreads();
            if (s + NSTG - 1 < NS) {
                uint32_t so = ((s + NSTG - 1) & (NSTG - 1)) * STG_B;
                uint64_t ko = (uint64_t)(s + NSTG - 1) * BKH * 2;
                cpa16(aS + so, aG + ko); cpa16(aS + so + 16, aG + ko + 16);
                cpa16(bS + so, bG + ko); cpa16(bS + so + 16, bG + ko + 16);
            }
            CPA_COMMIT();

            const uint32_t* A = (const uint32_t*)(AsB + (s & (NSTG - 1)) * STG_B);
            const uint32_t* B = (const uint32_t*)(BsB + (s & (NSTG - 1)) * STG_B);
#pragma unroll
            for (int kc = 0; kc < 2; kc++) {
                uint32_t a[4][4], b[4][2];
                const int kb = kc * 8;
#pragma unroll
                for (int mf = 0; mf < 4; mf++) {
                    int mb = wm * 64 + mf * 16 + g;
                    a[mf][0] = A[mb * 20 + kb + tg];
                    a[mf][1] = A[(mb + 8) * 20 + kb + tg];
                    a[mf][2] = A[mb * 20 + kb + tg + 4];
                    a[mf][3] = A[(mb + 8) * 20 + kb + tg + 4];
                }
#pragma unroll
                for (int nf = 0; nf < 4; nf++) {
                    int nb = wn * 32 + nf * 8 + g;
                    b[nf][0] = B[nb * 20 + kb + tg];
                    b[nf][1] = B[nb * 20 + kb + tg + 4];
                }
#pragma unroll
                for (int mf = 0; mf < 4; mf++)
#pragma unroll
                    for (int nf = 0; nf < 4; nf++) mma_f16(acc[mf][nf], a[mf], b[nf]);
            }
        }
        __syncthreads();

        // epilogue: up warps (wn>=2) stage accums via smem; gate warps apply silu*up
        float* up_s = (float*)sm;  // 128 x 64, stride 65 (overlaps ring stages)
        if (wn >= 2) {
#pragma unroll
            for (int mf = 0; mf < 4; mf++) {
#pragma unroll
                for (int nf = 0; nf < 4; nf++) {
                    int rr = wm * 64 + mf * 16 + g;
                    int c = (wn - 2) * 32 + nf * 8 + 2 * tg;
                    up_s[rr * 65 + c]           = acc[mf][nf][0];
                    up_s[rr * 65 + c + 1]       = acc[mf][nf][1];
                    up_s[(rr + 8) * 65 + c]     = acc[mf][nf][2];
                    up_s[(rr + 8) * 65 + c + 1] = acc[mf][nf][3];
                }
            }
        }
        __syncthreads();
        if (wn < 2) {
#pragma unroll
            for (int mf = 0; mf < 4; mf++) {
#pragma unroll
                for (int nf = 0; nf < 4; nf++) {
                    int rr = wm * 64 + mf * 16 + g;
                    int c = wn * 32 + nf * 8 + 2 * tg;
#pragma unroll
                    for (int half = 0; half < 2; half++) {
                        int r2 = rr + half * 8;
                        int grow = row0 + r2;
                        if (grow >= cnt) continue;
                        float gv0 = acc[mf][nf][half * 2 + 0];
                        float gv1 = acc[mf][nf][half * 2 + 1];
                        float u0 = up_s[r2 * 65 + c];
                        float u1 = up_s[r2 * 65 + c + 1];
                        float s0 = gv0 / (1.0f + __expf(-gv0));
                        float s1 = gv1 / (1.0f + __expf(-gv1));
                        __half2 h = __floats2half2_rn(s0 * u0, s1 * u1);
                        *(__half2*)(g_act + (size_t)(base + grow) * ID + nI + c) = h;
                    }
                }
            }
        }
    }
}

// GEMM2: out[tok] += w_row * (act @ w2^T) — combine fused via atomicAdd.
__global__ void __launch_bounds__(256, 2) gemm2_mma_kernel(float* __restrict__ out) {
    extern __shared__ char sm[];
    char* AsB = sm;
    char* BsB = sm + NSTG * STG_B;

    const int tid  = threadIdx.x;
    const int warp = tid >> 5;
    const int lane = tid & 31;
    const int wm = warp & 1;
    const int wn = warp >> 1;
    const int g  = lane >> 2;
    const int tg = lane & 3;

    const int lrow = tid >> 1;
    const int lcol = (tid & 1) * 16;

    const uint32_t aS = smem_u32(AsB) + (uint32_t)(lrow * PFH + lcol) * 2;
    const uint32_t bS = smem_u32(BsB) + (uint32_t)(lrow * PFH + lcol) * 2;

    const int NT = NE * (HD / 128) * (NROW / 128);  // 16384 virtual tiles

    for (int v = blockIdx.x; v < NT; v += PGRID) {
        const int e   = v / ((HD / 128) * (NROW / 128));
        const int r   = v % ((HD / 128) * (NROW / 128));
        const int row0 = (r & 127) * 128;          // row block fastest
        const int cnt = g_count[e];
        if (row0 >= cnt) continue;
        const int base = g_base[e];
        const int n0b = (r >> 7) * 128;

        __syncthreads();

        int gr = row0 + lrow; if (gr >= cnt) gr = cnt - 1;
        const uint64_t aG = (uint64_t)__cvta_generic_to_global(g_act + (size_t)(base + gr) * ID + lcol);
        const uint64_t bG = (uint64_t)__cvta_generic_to_global(g_w2h + ((size_t)e * HD + n0b + lrow) * ID + lcol);

        float acc[4][4][4];
#pragma unroll
        for (int i = 0; i < 4; i++)
#pragma unroll
            for (int j = 0; j < 4; j++)
#pragma unroll
                for (int q = 0; q < 4; q++) acc[i][j][q] = 0.f;

        const int NS = ID / BKH;  // 176
#pragma unroll
        for (int p = 0; p < NSTG - 1; p++) {
            uint32_t so = p * STG_B;
            uint64_t ko = (uint64_t)p * BKH * 2;
            cpa16(aS + so, aG + ko); cpa16(aS + so + 16, aG + ko + 16);
            cpa16(bS + so, bG + ko); cpa16(bS + so + 16, bG + ko + 16);
            CPA_COMMIT();
        }

        for (int s = 0; s < NS; s++) {
            CPA_WAIT(NSTG - 2);
            __syncthreads();
            if (s + NSTG - 1 < NS) {
                uint32_t so = ((s + NSTG - 1) & (NSTG - 1)) * STG_B;
                uint64_t ko = (uint64_t)(s + NSTG - 1) * BKH * 2;
                cpa16(aS + so, aG + ko); cpa16(aS + so + 16, aG + ko + 16);
                cpa16(bS + so, bG + ko); cpa16(bS + so + 16, bG + ko + 16);
            }
            CPA_COMMIT();

            const uint32_t* A = (const uint32_t*)(AsB + (s & (NSTG - 1)) * STG_B);
            const uint32_t* B = (const uint32_t*)(BsB + (s & (NSTG - 1)) * STG_B);
#pragma unroll
            for (int kc = 0; kc < 2; kc++) {
                uint32_t a[4][4], b[4][2];
                const int kb = kc * 8;
#pragma unroll
                for (int mf = 0; mf < 4; mf++) {
                    int mb = wm * 64 + mf * 16 + g;
                    a[mf][0] = A[mb * 20 + kb + tg];
                    a[mf][1] = A[(mb + 8) * 20 + kb + tg];
                    a[mf][2] = A[mb * 20 + kb + tg + 4];
                    a[mf][3] = A[(mb + 8) * 20 + kb + tg + 4];
                }
#pragma unroll
                for (int nf = 0; nf < 4; nf++) {
                    int nb = wn * 32 + nf * 8 + g;
                    b[nf][0] = B[nb * 20 + kb + tg];
                    b[nf][1] = B[nb * 20 + kb + tg + 4];
                }
#pragma unroll
                for (int mf = 0; mf < 4; mf++)
#pragma unroll
                    for (int nf = 0; nf < 4; nf++) mma_f16(acc[mf][nf], a[mf], b[nf]);
            }
        }

        // fused combine epilogue: out[tok, col] += wr * acc
#pragma unroll
        for (int mf = 0; mf < 4; mf++) {
#pragma unroll
            for (int nf = 0; nf < 4; nf++) {
                int rr = wm * 64 + mf * 16 + g;
                int c = wn * 32 + nf * 8 + 2 * tg;
#pragma unroll
                for (int half = 0; half < 2; half++) {
                    int r2 = rr + half * 8;
                    int grow = row0 + r2;
                    if (grow >= cnt) continue;
                    int tok2 = g_tok_of_row[base + grow];
                    float wr = g_w_of_row[base + grow];
                    float* op = out + (size_t)tok2 * HD + n0b + c;
                    atomicAdd(op,     wr * acc[mf][nf][half * 2 + 0]);
                    atomicAdd(op + 1, wr * acc[mf][nf][half * 2 + 1]);
                }
            }
        }
    }
}

// ---------------- launch ----------------
extern "C" void kernel_launch(void* const* d_in, const int* in_sizes, int n_in,
                              void* d_out, int out_size)
{
    const float* hidden = (const float*)d_in[0];
    const float* logits = (const float*)d_in[1];
    const float* w1 = (const float*)d_in[2];
    const float* w2 = (const float*)d_in[3];
    const float* w3 = (const float*)d_in[4];
    float* out = (float*)d_out;

    static int attr_done = 0;
    if (!attr_done) {
        cudaFuncSetAttribute(gemm1_mma_kernel, cudaFuncAttributeMaxDynamicSharedMemorySize, GEMM_SMEM);
        cudaFuncSetAttribute(gemm2_mma_kernel, cudaFuncAttributeMaxDynamicSharedMemorySize, GEMM_SMEM);
        attr_done = 1;
    }

    __half *xh_p, *w1_p, *w2_p, *w3_p;
    cudaGetSymbolAddress((void**)&xh_p, g_xh);
    cudaGetSymbolAddress((void**)&w1_p, g_w1h);
    cudaGetSymbolAddress((void**)&w2_p, g_w2h);
    cudaGetSymbolAddress((void**)&w3_p, g_w3h);

    // zero the output (combine is fused into GEMM2 via atomicAdd)
    cudaMemsetAsync(d_out, 0, (size_t)out_size * sizeof(float));

    {
        int n4 = TT * HD / 4;
        to_half_kernel<<<(n4 + 511) / 512, 256>>>((const float4*)hidden, (uint2*)xh_p, n4);
        int w4 = NE * ID * HD / 4;
        to_half_kernel<<<(w4 + 511) / 512, 256>>>((const float4*)w1, (uint2*)w1_p, w4);
        to_half_kernel<<<(w4 + 511) / 512, 256>>>((const float4*)w3, (uint2*)w3_p, w4);
        to_half_kernel<<<(w4 + 511) / 512, 256>>>((const float4*)w2, (uint2*)w2_p, w4);
    }

    zero_meta_kernel<<<1, 32>>>();
    route_count_kernel<<<(TT + 255) / 256, 256>>>(logits);
    scan_kernel<<<1, 1>>>();
    route_scatter_kernel<<<(TT + 255) / 256, 256>>>();

    gemm1_mma_kernel<<<PGRID, 256, GEMM_SMEM>>>();
    gemm2_mma_kernel<<<PGRID, 256, GEMM_SMEM>>>(out);
}

// round 9
// speedup vs baseline: 1.6378x; 1.6378x over previous
#include <cuda_runtime.h>
#include <cuda_fp16.h>
#include <cstdint>
#include <math.h>

#define TT 8192
#define NE 8
#define HD 2048
#define ID 5632
#define NROW (TT*2)

// ---------------- scratch (static device globals) ----------------
__device__ int    g_count[NE];
__device__ int    g_base[NE];
__device__ int    g_ctr[NE];
__device__ int    g_blkbase[NE + 1];       // packed row-block prefix (per 128 rows)
__device__ int    g_tok_e[TT*2];
__device__ float  g_tok_w[TT*2];
__device__ int    g_row_of[TT*2];
__device__ int    g_tok_of_row[NROW];
__device__ float  g_w_of_row[NROW];
__device__ __half g_xh [(size_t)TT*HD];
__device__ __half g_w1h[(size_t)NE*ID*HD];
__device__ __half g_w3h[(size_t)NE*ID*HD];
__device__ __half g_w2h[(size_t)NE*HD*ID];
__device__ __half g_act[(size_t)NROW*ID];

// ---------------- helpers ----------------
__device__ __forceinline__ void cpa16(uint32_t dst, uint64_t gsrc) {
    asm volatile("cp.async.cg.shared.global [%0], [%1], 16;" :: "r"(dst), "l"(gsrc));
}
#define CPA_COMMIT() asm volatile("cp.async.commit_group;" ::: "memory")
#define CPA_WAIT(n)  asm volatile("cp.async.wait_group %0;" :: "n"(n) : "memory")

__device__ __forceinline__ uint32_t smem_u32(const void* p) {
    uint32_t a;
    asm("{ .reg .u64 t; cvta.to.shared.u64 t, %1; cvt.u32.u64 %0, t; }" : "=r"(a) : "l"(p));
    return a;
}

__device__ __forceinline__ void mma_f16(float* c, const uint32_t* a, const uint32_t* b) {
    asm volatile(
        "mma.sync.aligned.m16n8k16.row.col.f32.f16.f16.f32 "
        "{%0,%1,%2,%3},{%4,%5,%6,%7},{%8,%9},{%0,%1,%2,%3};"
        : "+f"(c[0]), "+f"(c[1]), "+f"(c[2]), "+f"(c[3])
        : "r"(a[0]), "r"(a[1]), "r"(a[2]), "r"(a[3]), "r"(b[0]), "r"(b[1]));
}

// ---------------- routing ----------------
__global__ void zero_meta_kernel() { if (threadIdx.x < NE) g_count[threadIdx.x] = 0; }

__global__ void route_count_kernel(const float* __restrict__ logits) {
    int t = blockIdx.x * blockDim.x + threadIdx.x;
    if (t >= TT) return;
    float v[NE];
#pragma unroll
    for (int e = 0; e < NE; e++) v[e] = logits[t * NE + e];
    int i0 = 0; float m0 = v[0];
#pragma unroll
    for (int e = 1; e < NE; e++) if (v[e] > m0) { m0 = v[e]; i0 = e; }
    int i1 = -1; float m1 = -INFINITY;
#pragma unroll
    for (int e = 0; e < NE; e++) if (e != i0 && v[e] > m1) { m1 = v[e]; i1 = e; }
    float z = expf(m1 - m0);
    float w0 = 1.0f / (1.0f + z);
    g_tok_e[t*2+0] = i0; g_tok_e[t*2+1] = i1;
    g_tok_w[t*2+0] = w0; g_tok_w[t*2+1] = z * w0;
    atomicAdd(&g_count[i0], 1);
    atomicAdd(&g_count[i1], 1);
}

__global__ void scan_kernel() {
    int acc = 0, pb = 0;
    for (int e = 0; e < NE; e++) {
        g_base[e] = acc; acc += g_count[e]; g_ctr[e] = 0;
        g_blkbase[e] = pb; pb += (g_count[e] + 127) >> 7;
    }
    g_blkbase[NE] = pb;
}

__global__ void route_scatter_kernel() {
    int t = blockIdx.x * blockDim.x + threadIdx.x;
    if (t >= TT) return;
#pragma unroll
    for (int k = 0; k < 2; k++) {
        int e = g_tok_e[t*2+k];
        int slot = atomicAdd(&g_ctr[e], 1);
        int row = g_base[e] + slot;
        g_row_of[t*2+k] = row;
        g_tok_of_row[row] = t;
        g_w_of_row[row] = g_tok_w[t*2+k];
    }
}

// ---------------- fp32 -> fp16 convert (2 float4 per thread) ----------------
__global__ void to_half_kernel(const float4* __restrict__ in, uint2* __restrict__ out, int n4) {
    int i = (blockIdx.x * blockDim.x + threadIdx.x) * 2;
#pragma unroll
    for (int q = 0; q < 2; q++) {
        int j = i + q;
        if (j >= n4) return;
        float4 v = in[j];
        __half2 h0 = __floats2half2_rn(v.x, v.y);
        __half2 h1 = __floats2half2_rn(v.z, v.w);
        uint2 o;
        o.x = *reinterpret_cast<uint32_t*>(&h0);
        o.y = *reinterpret_cast<uint32_t*>(&h1);
        out[j] = o;
    }
}

// ---------------- GEMM kernels (fp16 m16n8k16, R7 core) ----------------
// Block 128(M) x 128(Bcols), BK=32 halves (64B/row), 8 warps (2x4), warp tile 64x32.
// 4-stage cp.async ring; rows padded to 40 halves (word stride 20 -> conflict-free).
// Grid: packed row-block index in blockIdx.x (fastest) -> no empty CTAs, L2 B-share.
#define BKH  32
#define PFH  40
#define TILE_H (128*PFH)                  // halves per tile per stage (5120)
#define STG_B  (TILE_H*2)                 // 10240 bytes
#define NSTG 4
#define GEMM_SMEM (2*NSTG*STG_B)          // 81920 bytes
#define GRID_X (NROW/128 + NE)             // worst-case packed block count (136)

// GEMM1: B rows 0..63 = w1 rows (gate), 64..127 = w3 rows (up), same 64 I-cols.
__global__ void __launch_bounds__(256, 2) gemm1_mma_kernel() {
    extern __shared__ char sm[];
    char* AsB = sm;
    char* BsB = sm + NSTG * STG_B;

    const int bx = blockIdx.x;
    if (bx >= g_blkbase[NE]) return;
    int e = 0;
#pragma unroll
    for (int k = 1; k < NE; k++) if (bx >= g_blkbase[k]) e = k;
    const int row0 = (bx - g_blkbase[e]) * 128;
    const int cnt = g_count[e];
    const int base = g_base[e];
    const int nI = blockIdx.y * 64;

    const int tid  = threadIdx.x;
    const int warp = tid >> 5;
    const int lane = tid & 31;
    const int wm = warp & 1;
    const int wn = warp >> 1;
    const int g  = lane >> 2;
    const int tg = lane & 3;

    const int lrow = tid >> 1;                 // 0..127
    const int lcol = (tid & 1) * 16;           // fp16 offset (0 or 16)

    int gr = row0 + lrow;
    int tok = (gr < cnt) ? g_tok_of_row[base + gr] : 0;
    const uint64_t aG = (uint64_t)__cvta_generic_to_global(g_xh + (size_t)tok * HD + lcol);
    const __half* bptr = (lrow < 64)
        ? g_w1h + ((size_t)e * ID + nI + lrow) * HD + lcol
        : g_w3h + ((size_t)e * ID + nI + (lrow - 64)) * HD + lcol;
    const uint64_t bG = (uint64_t)__cvta_generic_to_global(bptr);

    const uint32_t aS = smem_u32(AsB) + (uint32_t)(lrow * PFH + lcol) * 2;
    const uint32_t bS = smem_u32(BsB) + (uint32_t)(lrow * PFH + lcol) * 2;

    float acc[4][4][4];
#pragma unroll
    for (int i = 0; i < 4; i++)
#pragma unroll
        for (int j = 0; j < 4; j++)
#pragma unroll
            for (int q = 0; q < 4; q++) acc[i][j][q] = 0.f;

    const int NS = HD / BKH;  // 64
#pragma unroll
    for (int p = 0; p < NSTG - 1; p++) {
        uint32_t so = p * STG_B;
        uint64_t ko = (uint64_t)p * BKH * 2;
        cpa16(aS + so, aG + ko); cpa16(aS + so + 16, aG + ko + 16);
        cpa16(bS + so, bG + ko); cpa16(bS + so + 16, bG + ko + 16);
        CPA_COMMIT();
    }

    for (int s = 0; s < NS; s++) {
        CPA_WAIT(NSTG - 2);
        __syncthreads();
        if (s + NSTG - 1 < NS) {
            uint32_t so = ((s + NSTG - 1) & (NSTG - 1)) * STG_B;
            uint64_t ko = (uint64_t)(s + NSTG - 1) * BKH * 2;
            cpa16(aS + so, aG + ko); cpa16(aS + so + 16, aG + ko + 16);
            cpa16(bS + so, bG + ko); cpa16(bS + so + 16, bG + ko + 16);
        }
        CPA_COMMIT();

        const uint32_t* A = (const uint32_t*)(AsB + (s & (NSTG - 1)) * STG_B);
        const uint32_t* B = (const uint32_t*)(BsB + (s & (NSTG - 1)) * STG_B);
#pragma unroll
        for (int kc = 0; kc < 2; kc++) {          // two k16 chunks
            uint32_t a[4][4], b[4][2];
            const int kb = kc * 8;                // word offset
#pragma unroll
            for (int mf = 0; mf < 4; mf++) {
                int mb = wm * 64 + mf * 16 + g;
                a[mf][0] = A[mb * 20 + kb + tg];
                a[mf][1] = A[(mb + 8) * 20 + kb + tg];
                a[mf][2] = A[mb * 20 + kb + tg + 4];
                a[mf][3] = A[(mb + 8) * 20 + kb + tg + 4];
            }
#pragma unroll
            for (int nf = 0; nf < 4; nf++) {
                int nb = wn * 32 + nf * 8 + g;
                b[nf][0] = B[nb * 20 + kb + tg];
                b[nf][1] = B[nb * 20 + kb + tg + 4];
            }
#pragma unroll
            for (int mf = 0; mf < 4; mf++)
#pragma unroll
                for (int nf = 0; nf < 4; nf++) mma_f16(acc[mf][nf], a[mf], b[nf]);
        }
    }
    __syncthreads();

    // epilogue: up warps (wn>=2) stage accums via smem; gate warps apply silu*up
    float* up_s = (float*)sm;  // 128 x 64, stride 65 = 8320 floats (fits)
    if (wn >= 2) {
#pragma unroll
        for (int mf = 0; mf < 4; mf++) {
#pragma unroll
            for (int nf = 0; nf < 4; nf++) {
                int r = wm * 64 + mf * 16 + g;
                int c = (wn - 2) * 32 + nf * 8 + 2 * tg;
                up_s[r * 65 + c]           = acc[mf][nf][0];
                up_s[r * 65 + c + 1]       = acc[mf][nf][1];
                up_s[(r + 8) * 65 + c]     = acc[mf][nf][2];
                up_s[(r + 8) * 65 + c + 1] = acc[mf][nf][3];
            }
        }
    }
    __syncthreads();
    if (wn < 2) {
#pragma unroll
        for (int mf = 0; mf < 4; mf++) {
#pragma unroll
            for (int nf = 0; nf < 4; nf++) {
                int r = wm * 64 + mf * 16 + g;
                int c = wn * 32 + nf * 8 + 2 * tg;
#pragma unroll
                for (int half = 0; half < 2; half++) {
                    int rr = r + half * 8;
                    int grow = row0 + rr;
                    if (grow >= cnt) continue;
                    float gv0 = acc[mf][nf][half * 2 + 0];
                    float gv1 = acc[mf][nf][half * 2 + 1];
                    float u0 = up_s[rr * 65 + c];
                    float u1 = up_s[rr * 65 + c + 1];
                    float s0 = gv0 / (1.0f + __expf(-gv0));
                    float s1 = gv1 / (1.0f + __expf(-gv1));
                    __half2 h = __floats2half2_rn(s0 * u0, s1 * u1);
                    *(__half2*)(g_act + (size_t)(base + grow) * ID + nI + c) = h;
                }
            }
        }
    }
}

// GEMM2: out[tok] += w_row * (act @ w2^T) — combine fused via atomicAdd.
__global__ void __launch_bounds__(256, 2) gemm2_mma_kernel(float* __restrict__ out) {
    extern __shared__ char sm[];
    char* AsB = sm;
    char* BsB = sm + NSTG * STG_B;

    const int bx = blockIdx.x;
    if (bx >= g_blkbase[NE]) return;
    int e = 0;
#pragma unroll
    for (int k = 1; k < NE; k++) if (bx >= g_blkbase[k]) e = k;
    const int row0 = (bx - g_blkbase[e]) * 128;
    const int cnt = g_count[e];
    const int base = g_base[e];
    const int n0b = blockIdx.y * 128;

    const int tid  = threadIdx.x;
    const int warp = tid >> 5;
    const int lane = tid & 31;
    const int wm = warp & 1;
    const int wn = warp >> 1;
    const int g  = lane >> 2;
    const int tg = lane & 3;

    const int lrow = tid >> 1;
    const int lcol = (tid & 1) * 16;

    int gr = row0 + lrow; if (gr >= cnt) gr = cnt - 1;
    const uint64_t aG = (uint64_t)__cvta_generic_to_global(g_act + (size_t)(base + gr) * ID + lcol);
    const uint64_t bG = (uint64_t)__cvta_generic_to_global(g_w2h + ((size_t)e * HD + n0b + lrow) * ID + lcol);

    const uint32_t aS = smem_u32(AsB) + (uint32_t)(lrow * PFH + lcol) * 2;
    const uint32_t bS = smem_u32(BsB) + (uint32_t)(lrow * PFH + lcol) * 2;

    float acc[4][4][4];
#pragma unroll
    for (int i = 0; i < 4; i++)
#pragma unroll
        for (int j = 0; j < 4; j++)
#pragma unroll
            for (int q = 0; q < 4; q++) acc[i][j][q] = 0.f;

    const int NS = ID / BKH;  // 176
#pragma unroll
    for (int p = 0; p < NSTG - 1; p++) {
        uint32_t so = p * STG_B;
        uint64_t ko = (uint64_t)p * BKH * 2;
        cpa16(aS + so, aG + ko); cpa16(aS + so + 16, aG + ko + 16);
        cpa16(bS + so, bG + ko); cpa16(bS + so + 16, bG + ko + 16);
        CPA_COMMIT();
    }

    for (int s = 0; s < NS; s++) {
        CPA_WAIT(NSTG - 2);
        __syncthreads();
        if (s + NSTG - 1 < NS) {
            uint32_t so = ((s + NSTG - 1) & (NSTG - 1)) * STG_B;
            uint64_t ko = (uint64_t)(s + NSTG - 1) * BKH * 2;
            cpa16(aS + so, aG + ko); cpa16(aS + so + 16, aG + ko + 16);
            cpa16(bS + so, bG + ko); cpa16(bS + so + 16, bG + ko + 16);
        }
        CPA_COMMIT();

        const uint32_t* A = (const uint32_t*)(AsB + (s & (NSTG - 1)) * STG_B);
        const uint32_t* B = (const uint32_t*)(BsB + (s & (NSTG - 1)) * STG_B);
#pragma unroll
        for (int kc = 0; kc < 2; kc++) {
            uint32_t a[4][4], b[4][2];
            const int kb = kc * 8;
#pragma unroll
            for (int mf = 0; mf < 4; mf++) {
                int mb = wm * 64 + mf * 16 + g;
                a[mf][0] = A[mb * 20 + kb + tg];
                a[mf][1] = A[(mb + 8) * 20 + kb + tg];
                a[mf][2] = A[mb * 20 + kb + tg + 4];
                a[mf][3] = A[(mb + 8) * 20 + kb + tg + 4];
            }
#pragma unroll
            for (int nf = 0; nf < 4; nf++) {
                int nb = wn * 32 + nf * 8 + g;
                b[nf][0] = B[nb * 20 + kb + tg];
                b[nf][1] = B[nb * 20 + kb + tg + 4];
            }
#pragma unroll
            for (int mf = 0; mf < 4; mf++)
#pragma unroll
                for (int nf = 0; nf < 4; nf++) mma_f16(acc[mf][nf], a[mf], b[nf]);
        }
    }

    // fused combine epilogue: out[tok, col] += wr * acc
#pragma unroll
    for (int mf = 0; mf < 4; mf++) {
#pragma unroll
        for (int nf = 0; nf < 4; nf++) {
            int r = wm * 64 + mf * 16 + g;
            int c = wn * 32 + nf * 8 + 2 * tg;
#pragma unroll
            for (int half = 0; half < 2; half++) {
                int rr = r + half * 8;
                int grow = row0 + rr;
                if (grow >= cnt) continue;
                int tok2 = g_tok_of_row[base + grow];
                float wr = g_w_of_row[base + grow];
                float* op = out + (size_t)tok2 * HD + n0b + c;
                atomicAdd(op,     wr * acc[mf][nf][half * 2 + 0]);
                atomicAdd(op + 1, wr * acc[mf][nf][half * 2 + 1]);
            }
        }
    }
}

// ---------------- launch ----------------
extern "C" void kernel_launch(void* const* d_in, const int* in_sizes, int n_in,
                              void* d_out, int out_size)
{
    const float* hidden = (const float*)d_in[0];
    const float* logits = (const float*)d_in[1];
    const float* w1 = (const float*)d_in[2];
    const float* w2 = (const float*)d_in[3];
    const float* w3 = (const float*)d_in[4];
    float* out = (float*)d_out;

    static int attr_done = 0;
    if (!attr_done) {
        cudaFuncSetAttribute(gemm1_mma_kernel, cudaFuncAttributeMaxDynamicSharedMemorySize, GEMM_SMEM);
        cudaFuncSetAttribute(gemm2_mma_kernel, cudaFuncAttributeMaxDynamicSharedMemorySize, GEMM_SMEM);
        attr_done = 1;
    }

    __half *xh_p, *w1_p, *w2_p, *w3_p;
    cudaGetSymbolAddress((void**)&xh_p, g_xh);
    cudaGetSymbolAddress((void**)&w1_p, g_w1h);
    cudaGetSymbolAddress((void**)&w2_p, g_w2h);
    cudaGetSymbolAddress((void**)&w3_p, g_w3h);

    // zero the output (combine is fused into GEMM2 via atomicAdd)
    cudaMemsetAsync(d_out, 0, (size_t)out_size * sizeof(float));

    {
        int n4 = TT * HD / 4;
        to_half_kernel<<<(n4 + 511) / 512, 256>>>((const float4*)hidden, (uint2*)xh_p, n4);
        int w4 = NE * ID * HD / 4;
        to_half_kernel<<<(w4 + 511) / 512, 256>>>((const float4*)w1, (uint2*)w1_p, w4);
        to_half_kernel<<<(w4 + 511) / 512, 256>>>((const float4*)w3, (uint2*)w3_p, w4);
        to_half_kernel<<<(w4 + 511) / 512, 256>>>((const float4*)w2, (uint2*)w2_p, w4);
    }

    zero_meta_kernel<<<1, 32>>>();
    route_count_kernel<<<(TT + 255) / 256, 256>>>(logits);
    scan_kernel<<<1, 1>>>();
    route_scatter_kernel<<<(TT + 255) / 256, 256>>>();

    dim3 g1(GRID_X, ID / 64, NE > 0 ? 1 : 1);   // packed row-blocks x I-cols
    gemm1_mma_kernel<<<dim3(GRID_X, ID / 64, 1), 256, GEMM_SMEM>>>();

    gemm2_mma_kernel<<<dim3(GRID_X, HD / 128, 1), 256, GEMM_SMEM>>>(out);
}

// round 10
// speedup vs baseline: 1.6429x; 1.0031x over previous
#include <cuda_runtime.h>
#include <cuda_fp16.h>
#include <cstdint>
#include <math.h>

#define TT 8192
#define NE 8
#define HD 2048
#define ID 5632
#define NROW (TT*2)

// ---------------- scratch (static device globals) ----------------
__device__ int    g_count[NE];
__device__ int    g_base[NE];
__device__ int    g_ctr[NE];
__device__ int    g_blkbase[NE + 1];       // packed row-block prefix (per 128 rows)
__device__ int    g_tok_e[TT*2];
__device__ float  g_tok_w[TT*2];
__device__ int    g_row_of[TT*2];
__device__ int    g_tok_of_row[NROW];
__device__ float  g_w_of_row[NROW];
__device__ __half g_xh [(size_t)TT*HD];
__device__ __half g_w1h[(size_t)NE*ID*HD];
__device__ __half g_w3h[(size_t)NE*ID*HD];
__device__ __half g_w2h[(size_t)NE*HD*ID];
__device__ __half g_act[(size_t)NROW*ID];

// ---------------- helpers ----------------
__device__ __forceinline__ void cpa16(uint32_t dst, uint64_t gsrc) {
    asm volatile("cp.async.cg.shared.global [%0], [%1], 16;" :: "r"(dst), "l"(gsrc));
}
#define CPA_COMMIT() asm volatile("cp.async.commit_group;" ::: "memory")
#define CPA_WAIT(n)  asm volatile("cp.async.wait_group %0;" :: "n"(n) : "memory")

__device__ __forceinline__ uint32_t smem_u32(const void* p) {
    uint32_t a;
    asm("{ .reg .u64 t; cvta.to.shared.u64 t, %1; cvt.u32.u64 %0, t; }" : "=r"(a) : "l"(p));
    return a;
}

__device__ __forceinline__ void mma_f16(float* c, const uint32_t* a, const uint32_t* b) {
    asm volatile(
        "mma.sync.aligned.m16n8k16.row.col.f32.f16.f16.f32 "
        "{%0,%1,%2,%3},{%4,%5,%6,%7},{%8,%9},{%0,%1,%2,%3};"
        : "+f"(c[0]), "+f"(c[1]), "+f"(c[2]), "+f"(c[3])
        : "r"(a[0]), "r"(a[1]), "r"(a[2]), "r"(a[3]), "r"(b[0]), "r"(b[1]));
}

// ---------------- routing ----------------
__global__ void zero_meta_kernel() { if (threadIdx.x < NE) g_count[threadIdx.x] = 0; }

__global__ void route_count_kernel(const float* __restrict__ logits) {
    int t = blockIdx.x * blockDim.x + threadIdx.x;
    if (t >= TT) return;
    float v[NE];
#pragma unroll
    for (int e = 0; e < NE; e++) v[e] = logits[t * NE + e];
    int i0 = 0; float m0 = v[0];
#pragma unroll
    for (int e = 1; e < NE; e++) if (v[e] > m0) { m0 = v[e]; i0 = e; }
    int i1 = -1; float m1 = -INFINITY;
#pragma unroll
    for (int e = 0; e < NE; e++) if (e != i0 && v[e] > m1) { m1 = v[e]; i1 = e; }
    float z = expf(m1 - m0);
    float w0 = 1.0f / (1.0f + z);
    g_tok_e[t*2+0] = i0; g_tok_e[t*2+1] = i1;
    g_tok_w[t*2+0] = w0; g_tok_w[t*2+1] = z * w0;
    atomicAdd(&g_count[i0], 1);
    atomicAdd(&g_count[i1], 1);
}

__global__ void scan_kernel() {
    int acc = 0, pb = 0;
    for (int e = 0; e < NE; e++) {
        g_base[e] = acc; acc += g_count[e]; g_ctr[e] = 0;
        g_blkbase[e] = pb; pb += (g_count[e] + 127) >> 7;
    }
    g_blkbase[NE] = pb;
}

__global__ void route_scatter_kernel() {
    int t = blockIdx.x * blockDim.x + threadIdx.x;
    if (t >= TT) return;
#pragma unroll
    for (int k = 0; k < 2; k++) {
        int e = g_tok_e[t*2+k];
        int slot = atomicAdd(&g_ctr[e], 1);
        int row = g_base[e] + slot;
        g_row_of[t*2+k] = row;
        g_tok_of_row[row] = t;
        g_w_of_row[row] = g_tok_w[t*2+k];
    }
}

// ---------------- fp32 -> fp16 convert (2 float4 per thread) ----------------
__global__ void to_half_kernel(const float4* __restrict__ in, uint2* __restrict__ out, int n4) {
    int i = (blockIdx.x * blockDim.x + threadIdx.x) * 2;
#pragma unroll
    for (int q = 0; q < 2; q++) {
        int j = i + q;
        if (j >= n4) return;
        float4 v = in[j];
        __half2 h0 = __floats2half2_rn(v.x, v.y);
        __half2 h1 = __floats2half2_rn(v.z, v.w);
        uint2 o;
        o.x = *reinterpret_cast<uint32_t*>(&h0);
        o.y = *reinterpret_cast<uint32_t*>(&h1);
        out[j] = o;
    }
}

// ---------------- GEMM kernels (fp16 m16n8k16) ----------------
// Block 128(M) x 128(Bcols), BK=32 halves (64B/row), 8 warps (2x4), warp tile 64x32.
// 4-stage cp.async ring; rows padded to 40 halves (word stride 20 -> conflict-free).
// Grid: packed row-block index in blockIdx.x (fastest) -> no empty CTAs, L2 B-share.
#define BKH  32
#define PFH  40
#define TILE_H (128*PFH)                  // halves per tile per stage (5120)
#define STG_B  (TILE_H*2)                 // 10240 bytes
#define NSTG 4
#define GEMM_SMEM (2*NSTG*STG_B)          // 81920 bytes
#define GRID_X (NROW/128 + NE)             // worst-case packed block count (136)

// GEMM1: B rows 0..63 = w1 rows (gate), 64..127 = w3 rows (up), same 64 I-cols.
__global__ void __launch_bounds__(256, 2) gemm1_mma_kernel() {
    extern __shared__ char sm[];
    char* AsB = sm;
    char* BsB = sm + NSTG * STG_B;

    const int bx = blockIdx.x;
    if (bx >= g_blkbase[NE]) return;
    int e = 0;
#pragma unroll
    for (int k = 1; k < NE; k++) if (bx >= g_blkbase[k]) e = k;
    const int row0 = (bx - g_blkbase[e]) * 128;
    const int cnt = g_count[e];
    const int base = g_base[e];
    const int nI = blockIdx.y * 64;

    const int tid  = threadIdx.x;
    const int warp = tid >> 5;
    const int lane = tid & 31;
    const int wm = warp & 1;
    const int wn = warp >> 1;
    const int g  = lane >> 2;
    const int tg = lane & 3;

    const int lrow = tid >> 1;                 // 0..127
    const int lcol = (tid & 1) * 16;           // fp16 offset (0 or 16)

    int gr = row0 + lrow;
    int tok = (gr < cnt) ? g_tok_of_row[base + gr] : 0;
    const uint64_t aG = (uint64_t)__cvta_generic_to_global(g_xh + (size_t)tok * HD + lcol);
    const __half* bptr = (lrow < 64)
        ? g_w1h + ((size_t)e * ID + nI + lrow) * HD + lcol
        : g_w3h + ((size_t)e * ID + nI + (lrow - 64)) * HD + lcol;
    const uint64_t bG = (uint64_t)__cvta_generic_to_global(bptr);

    const uint32_t aS = smem_u32(AsB) + (uint32_t)(lrow * PFH + lcol) * 2;
    const uint32_t bS = smem_u32(BsB) + (uint32_t)(lrow * PFH + lcol) * 2;

    float acc[4][4][4];
#pragma unroll
    for (int i = 0; i < 4; i++)
#pragma unroll
        for (int j = 0; j < 4; j++)
#pragma unroll
            for (int q = 0; q < 4; q++) acc[i][j][q] = 0.f;

    const int NS = HD / BKH;  // 64
#pragma unroll
    for (int p = 0; p < NSTG - 1; p++) {
        uint32_t so = p * STG_B;
        uint64_t ko = (uint64_t)p * BKH * 2;
        cpa16(aS + so, aG + ko); cpa16(aS + so + 16, aG + ko + 16);
        cpa16(bS + so, bG + ko); cpa16(bS + so + 16, bG + ko + 16);
        CPA_COMMIT();
    }

    for (int s = 0; s < NS; s++) {
        CPA_WAIT(NSTG - 2);
        __syncthreads();
        if (s + NSTG - 1 < NS) {
            uint32_t so = ((s + NSTG - 1) & (NSTG - 1)) * STG_B;
            uint64_t ko = (uint64_t)(s + NSTG - 1) * BKH * 2;
            cpa16(aS + so, aG + ko); cpa16(aS + so + 16, aG + ko + 16);
            cpa16(bS + so, bG + ko); cpa16(bS + so + 16, bG + ko + 16);
        }
        CPA_COMMIT();

        const uint32_t* A = (const uint32_t*)(AsB + (s & (NSTG - 1)) * STG_B);
        const uint32_t* B = (const uint32_t*)(BsB + (s & (NSTG - 1)) * STG_B);
#pragma unroll
        for (int kc = 0; kc < 2; kc++) {          // two k16 chunks
            uint32_t a[4][4], b[4][2];
            const int kb = kc * 8;                // word offset
#pragma unroll
            for (int mf = 0; mf < 4; mf++) {
                int mb = wm * 64 + mf * 16 + g;
                a[mf][0] = A[mb * 20 + kb + tg];
                a[mf][1] = A[(mb + 8) * 20 + kb + tg];
                a[mf][2] = A[mb * 20 + kb + tg + 4];
                a[mf][3] = A[(mb + 8) * 20 + kb + tg + 4];
            }
#pragma unroll
            for (int nf = 0; nf < 4; nf++) {
                int nb = wn * 32 + nf * 8 + g;
                b[nf][0] = B[nb * 20 + kb + tg];
                b[nf][1] = B[nb * 20 + kb + tg + 4];
            }
#pragma unroll
            for (int mf = 0; mf < 4; mf++)
#pragma unroll
                for (int nf = 0; nf < 4; nf++) mma_f16(acc[mf][nf], a[mf], b[nf]);
        }
    }
    __syncthreads();

    // epilogue: up warps (wn>=2) stage accums via smem; gate warps apply silu*up
    float* up_s = (float*)sm;  // 128 x 64, stride 65 = 8320 floats (fits)
    if (wn >= 2) {
#pragma unroll
        for (int mf = 0; mf < 4; mf++) {
#pragma unroll
            for (int nf = 0; nf < 4; nf++) {
                int r = wm * 64 + mf * 16 + g;
                int c = (wn - 2) * 32 + nf * 8 + 2 * tg;
                up_s[r * 65 + c]           = acc[mf][nf][0];
                up_s[r * 65 + c + 1]       = acc[mf][nf][1];
                up_s[(r + 8) * 65 + c]     = acc[mf][nf][2];
                up_s[(r + 8) * 65 + c + 1] = acc[mf][nf][3];
            }
        }
    }
    __syncthreads();
    if (wn < 2) {
#pragma unroll
        for (int mf = 0; mf < 4; mf++) {
#pragma unroll
            for (int nf = 0; nf < 4; nf++) {
                int r = wm * 64 + mf * 16 + g;
                int c = wn * 32 + nf * 8 + 2 * tg;
#pragma unroll
                for (int half = 0; half < 2; half++) {
                    int rr = r + half * 8;
                    int grow = row0 + rr;
                    if (grow >= cnt) continue;
                    float gv0 = acc[mf][nf][half * 2 + 0];
                    float gv1 = acc[mf][nf][half * 2 + 1];
                    float u0 = up_s[rr * 65 + c];
                    float u1 = up_s[rr * 65 + c + 1];
                    float s0 = gv0 / (1.0f + __expf(-gv0));
                    float s1 = gv1 / (1.0f + __expf(-gv1));
                    __half2 h = __floats2half2_rn(s0 * u0, s1 * u1);
                    *(__half2*)(g_act + (size_t)(base + grow) * ID + nI + c) = h;
                }
            }
        }
    }
}

// GEMM2: out[tok] += w_row * (act @ w2^T) — combine fused via atomicAdd.
__global__ void __launch_bounds__(256, 2) gemm2_mma_kernel(float* __restrict__ out) {
    extern __shared__ char sm[];
    char* AsB = sm;
    char* BsB = sm + NSTG * STG_B;

    const int bx = blockIdx.x;
    if (bx >= g_blkbase[NE]) return;
    int e = 0;
#pragma unroll
    for (int k = 1; k < NE; k++) if (bx >= g_blkbase[k]) e = k;
    const int row0 = (bx - g_blkbase[e]) * 128;
    const int cnt = g_count[e];
    const int base = g_base[e];
    const int n0b = blockIdx.y * 128;

    const int tid  = threadIdx.x;
    const int warp = tid >> 5;
    const int lane = tid & 31;
    const int wm = warp & 1;
    const int wn = warp >> 1;
    const int g  = lane >> 2;
    const int tg = lane & 3;

    const int lrow = tid >> 1;
    const int lcol = (tid & 1) * 16;

    int gr = row0 + lrow; if (gr >= cnt) gr = cnt - 1;
    const uint64_t aG = (uint64_t)__cvta_generic_to_global(g_act + (size_t)(base + gr) * ID + lcol);
    const uint64_t bG = (uint64_t)__cvta_generic_to_global(g_w2h + ((size_t)e * HD + n0b + lrow) * ID + lcol);

    const uint32_t aS = smem_u32(AsB) + (uint32_t)(lrow * PFH + lcol) * 2;
    const uint32_t bS = smem_u32(BsB) + (uint32_t)(lrow * PFH + lcol) * 2;

    float acc[4][4][4];
#pragma unroll
    for (int i = 0; i < 4; i++)
#pragma unroll
        for (int j = 0; j < 4; j++)
#pragma unroll
            for (int q = 0; q < 4; q++) acc[i][j][q] = 0.f;

    const int NS = ID / BKH;  // 176
#pragma unroll
    for (int p = 0; p < NSTG - 1; p++) {
        uint32_t so = p * STG_B;
        uint64_t ko = (uint64_t)p * BKH * 2;
        cpa16(aS + so, aG + ko); cpa16(aS + so + 16, aG + ko + 16);
        cpa16(bS + so, bG + ko); cpa16(bS + so + 16, bG + ko + 16);
        CPA_COMMIT();
    }

    for (int s = 0; s < NS; s++) {
        CPA_WAIT(NSTG - 2);
        __syncthreads();
        if (s + NSTG - 1 < NS) {
            uint32_t so = ((s + NSTG - 1) & (NSTG - 1)) * STG_B;
            uint64_t ko = (uint64_t)(s + NSTG - 1) * BKH * 2;
            cpa16(aS + so, aG + ko); cpa16(aS + so + 16, aG + ko + 16);
            cpa16(bS + so, bG + ko); cpa16(bS + so + 16, bG + ko + 16);
        }
        CPA_COMMIT();

        const uint32_t* A = (const uint32_t*)(AsB + (s & (NSTG - 1)) * STG_B);
        const uint32_t* B = (const uint32_t*)(BsB + (s & (NSTG - 1)) * STG_B);
#pragma unroll
        for (int kc = 0; kc < 2; kc++) {
            uint32_t a[4][4], b[4][2];
            const int kb = kc * 8;
#pragma unroll
            for (int mf = 0; mf < 4; mf++) {
                int mb = wm * 64 + mf * 16 + g;
                a[mf][0] = A[mb * 20 + kb + tg];
                a[mf][1] = A[(mb + 8) * 20 + kb + tg];
                a[mf][2] = A[mb * 20 + kb + tg + 4];
                a[mf][3] = A[(mb + 8) * 20 + kb + tg + 4];
            }
#pragma unroll
            for (int nf = 0; nf < 4; nf++) {
                int nb = wn * 32 + nf * 8 + g;
                b[nf][0] = B[nb * 20 + kb + tg];
                b[nf][1] = B[nb * 20 + kb + tg + 4];
            }
#pragma unroll
            for (int mf = 0; mf < 4; mf++)
#pragma unroll
                for (int nf = 0; nf < 4; nf++) mma_f16(acc[mf][nf], a[mf], b[nf]);
        }
    }

    // fused combine epilogue: out[tok, col] += wr * acc
#pragma unroll
    for (int mf = 0; mf < 4; mf++) {
#pragma unroll
        for (int nf = 0; nf < 4; nf++) {
            int r = wm * 64 + mf * 16 + g;
            int c = wn * 32 + nf * 8 + 2 * tg;
#pragma unroll
            for (int half = 0; half < 2; half++) {
                int rr = r + half * 8;
                int grow = row0 + rr;
                if (grow >= cnt) continue;
                int tok2 = g_tok_of_row[base + grow];
                float wr = g_w_of_row[base + grow];
                float* op = out + (size_t)tok2 * HD + n0b + c;
                atomicAdd(op,     wr * acc[mf][nf][half * 2 + 0]);
                atomicAdd(op + 1, wr * acc[mf][nf][half * 2 + 1]);
            }
        }
    }
}

// ---------------- launch (fork-join graph branches) ----------------
extern "C" void kernel_launch(void* const* d_in, const int* in_sizes, int n_in,
                              void* d_out, int out_size)
{
    const float* hidden = (const float*)d_in[0];
    const float* logits = (const float*)d_in[1];
    const float* w1 = (const float*)d_in[2];
    const float* w2 = (const float*)d_in[3];
    const float* w3 = (const float*)d_in[4];
    float* out = (float*)d_out;

    static int init_done = 0;
    static cudaStream_t sA, sB;
    static cudaEvent_t evRoot, evA, evB;
    if (!init_done) {
        cudaFuncSetAttribute(gemm1_mma_kernel, cudaFuncAttributeMaxDynamicSharedMemorySize, GEMM_SMEM);
        cudaFuncSetAttribute(gemm2_mma_kernel, cudaFuncAttributeMaxDynamicSharedMemorySize, GEMM_SMEM);
        cudaStreamCreateWithFlags(&sA, cudaStreamNonBlocking);
        cudaStreamCreateWithFlags(&sB, cudaStreamNonBlocking);
        cudaEventCreateWithFlags(&evRoot, cudaEventDisableTiming);
        cudaEventCreateWithFlags(&evA, cudaEventDisableTiming);
        cudaEventCreateWithFlags(&evB, cudaEventDisableTiming);
        init_done = 1;
    }

    __half *xh_p, *w1_p, *w2_p, *w3_p;
    cudaGetSymbolAddress((void**)&xh_p, g_xh);
    cudaGetSymbolAddress((void**)&w1_p, g_w1h);
    cudaGetSymbolAddress((void**)&w2_p, g_w2h);
    cudaGetSymbolAddress((void**)&w3_p, g_w3h);

    // fork: root event on the capture (default) stream
    cudaEventRecord(evRoot, 0);
    cudaStreamWaitEvent(sA, evRoot, 0);
    cudaStreamWaitEvent(sB, evRoot, 0);

    // branch A (sA): routing chain — hidden under the main-stream converts
    zero_meta_kernel<<<1, 32, 0, sA>>>();
    route_count_kernel<<<(TT + 255) / 256, 256, 0, sA>>>(logits);
    scan_kernel<<<1, 1, 0, sA>>>();
    route_scatter_kernel<<<(TT + 255) / 256, 256, 0, sA>>>();
    cudaEventRecord(evA, sA);

    // branch B (sB): w2 convert + out memset — hidden under GEMM1
    {
        int w4 = NE * ID * HD / 4;
        to_half_kernel<<<(w4 + 511) / 512, 256, 0, sB>>>((const float4*)w2, (uint2*)w2_p, w4);
        cudaMemsetAsync(d_out, 0, (size_t)out_size * sizeof(float), sB);
        cudaEventRecord(evB, sB);
    }

    // main stream: converts needed by GEMM1
    {
        int n4 = TT * HD / 4;
        to_half_kernel<<<(n4 + 511) / 512, 256>>>((const float4*)hidden, (uint2*)xh_p, n4);
        int w4 = NE * ID * HD / 4;
        to_half_kernel<<<(w4 + 511) / 512, 256>>>((const float4*)w1, (uint2*)w1_p, w4);
        to_half_kernel<<<(w4 + 511) / 512, 256>>>((const float4*)w3, (uint2*)w3_p, w4);
    }

    // join routing -> GEMM1
    cudaStreamWaitEvent(0, evA, 0);
    gemm1_mma_kernel<<<dim3(GRID_X, ID / 64, 1), 256, GEMM_SMEM>>>();

    // join w2 convert + memset -> GEMM2
    cudaStreamWaitEvent(0, evB, 0);
    gemm2_mma_kernel<<<dim3(GRID_X, HD / 128, 1), 256, GEMM_SMEM>>>(out);
}